// round 2
// baseline (speedup 1.0000x reference)
#include <cuda_runtime.h>
#include <cuda_bf16.h>

// PLIF spiking neuron: mem = mem*sigmoid(tau[c]) + x[t]; spike = (mem-1)>0;
// mem = (1-spike)*mem.  x: [B=32, T=8, C=128, H=32, W=32] f32, tau: [C] f32.
// Pure HBM-streaming: 134 MB in + 134 MB out (~268 MB total -> ~45 us floor
// at ~6.3 TB/s LTS cap). One thread = 4 consecutive spatial positions
// (float4); all 8 timesteps front-batched into registers (MLP_p1 = 8),
// recurrence in registers, 8 vectorized stores.

#define PLIF_T    8
#define PLIF_HW   1024                     // 32*32   = 2^10
#define PLIF_CHW  131072                   // 128*HW  = 2^17

__global__ __launch_bounds__(256) void PLIF_73538430042799_kernel(
    const float* __restrict__ x,
    const float* __restrict__ tau,
    float* __restrict__ out,
    int n_threads)                          // B*CHW/4 = 1,048,576
{
    int tid = blockIdx.x * blockDim.x + threadIdx.x;
    if (tid >= n_threads) return;

    int i = tid << 2;                       // element index within [0, B*CHW)
    int b = i >> 17;                        // i / CHW
    int r = i & (PLIF_CHW - 1);             // i % CHW
    int c = r >> 10;                        // channel = r / HW

    // sigmoid of per-channel leak. tau is 512 B -> L2/L1 resident.
    float tau_s = 1.0f / (1.0f + expf(-__ldg(&tau[c])));

    size_t base = (size_t)b * (PLIF_T * PLIF_CHW) + (size_t)r;
    const float4* xp = reinterpret_cast<const float4*>(x + base);
    float4*       op = reinterpret_cast<float4*>(out + base);
    const int t_stride4 = PLIF_CHW / 4;     // float4 stride between timesteps

    // Front-batch all T loads -> 8 outstanding LDG.128 per thread
    float4 v[PLIF_T];
#pragma unroll
    for (int t = 0; t < PLIF_T; ++t)
        v[t] = xp[t * t_stride4];

    float m0 = 0.f, m1 = 0.f, m2 = 0.f, m3 = 0.f;

#pragma unroll
    for (int t = 0; t < PLIF_T; ++t) {
        m0 = m0 * tau_s + v[t].x;
        m1 = m1 * tau_s + v[t].y;
        m2 = m2 * tau_s + v[t].z;
        m3 = m3 * tau_s + v[t].w;

        float s0 = (m0 - 1.0f) > 0.0f ? 1.0f : 0.0f;
        float s1 = (m1 - 1.0f) > 0.0f ? 1.0f : 0.0f;
        float s2 = (m2 - 1.0f) > 0.0f ? 1.0f : 0.0f;
        float s3 = (m3 - 1.0f) > 0.0f ? 1.0f : 0.0f;

        // hard reset: spiked neurons zero their membrane
        m0 = s0 > 0.f ? 0.f : m0;
        m1 = s1 > 0.f ? 0.f : m1;
        m2 = s2 > 0.f ? 0.f : m2;
        m3 = s3 > 0.f ? 0.f : m3;

        float4 sp; sp.x = s0; sp.y = s1; sp.z = s2; sp.w = s3;
        op[t * t_stride4] = sp;
    }
}

extern "C" void kernel_launch(void* const* d_in, const int* in_sizes, int n_in,
                              void* d_out, int out_size)
{
    const float* x   = (const float*)d_in[0];   // [B,T,C,H,W] f32
    const float* tau = (const float*)d_in[1];   // [C] f32
    float* out = (float*)d_out;

    int n_elems   = in_sizes[0];                 // B*T*C*H*W = 33,554,432
    int n_threads = n_elems / PLIF_T / 4;        // 1,048,576 (exact)

    int block = 256;
    int grid  = (n_threads + block - 1) / block; // 4096
    PLIF_73538430042799_kernel<<<grid, block>>>(x, tau, out, n_threads);
}